// round 14
// baseline (speedup 1.0000x reference)
#include <cuda_runtime.h>
#include <math.h>

#define PAD 68
#define ARR (64 * PAD)
#define SMEM_FLOATS (3 * ARR + 32)
#define SMEM_BYTES (SMEM_FLOATS * 4)

typedef unsigned long long u64;

// column-softmaxed weights, o-major: g_wT[o*64 + i] = w[i][o]
__device__ float g_wT[64 * 64];

static __device__ __forceinline__ u64 ffma2(u64 a, u64 b, u64 c) {
    u64 d; asm("fma.rn.f32x2 %0,%1,%2,%3;" : "=l"(d) : "l"(a), "l"(b), "l"(c)); return d;
}
static __device__ __forceinline__ float hadd2(u64 v) {
    float lo, hi; asm("mov.b64 {%0,%1},%2;" : "=f"(lo), "=f"(hi) : "l"(v));
    return lo + hi;
}

// acos via A&S 4.4.45 7-term poly, Estrin form: abs err ~2e-8 on [-1,1]
// Input pre-clamped to |x| <= 1-1e-7, so om >= 1e-7 (rsqrt safe).
static __device__ __forceinline__ float acos_fast(float x) {
    float ax = fabsf(x);
    float om = 1.0f - ax;
    float s = om * rsqrtf(om);   // sqrt(1-ax), MUFU issued early
    float x2 = ax * ax;
    float x4 = x2 * x2;
    float p01 = fmaf(ax, -0.2145988016f, 1.5707963050f);
    float p23 = fmaf(ax, -0.0501743046f, 0.0889789874f);
    float p45 = fmaf(ax, -0.0170881256f, 0.0308918810f);
    float p67 = fmaf(ax, -0.0012624911f, 0.0066700901f);
    float q0 = fmaf(p23, x2, p01);
    float q1 = fmaf(p67, x2, p45);
    float p = fmaf(q1, x4, q0);
    float r = p * s;
    return (x < 0.0f) ? 3.14159265358979f - r : r;
}

__global__ void wprep_kernel(const float* __restrict__ wraw) {
    int o = threadIdx.x;  // 64 threads, one output column each
    float s = 0.f;
    #pragma unroll 8
    for (int i = 0; i < 64; ++i) s += expf(wraw[i * 64 + o]);
    float inv = 1.0f / s;
    #pragma unroll 8
    for (int i = 0; i < 64; ++i) g_wT[o * 64 + i] = expf(wraw[i * 64 + o]) * inv;
}

__global__ __launch_bounds__(128, 4) void mfd_kernel(const float* __restrict__ xg,
                                                     float* __restrict__ out) {
    extern __shared__ float sm[];
    float* Xs = sm;              // [64][PAD]  x rows (dd-contiguous), read-only
    float* XT = Xs + ARR;        // [64][PAD]  x transposed (i-contiguous), read-only
    float* Ws = XT + ARR;        // [64][PAD]  A (iter input) <-> F (mid-iter), warp rows

    const int n   = blockIdx.x;
    const int tid = threadIdx.x;
    const int oc  = tid >> 4;    // 0..7  (warp = {2w, 2w+1} oc values)
    const int ic  = tid & 15;    // 0..15

    // ---- load x tile (coalesced float4) ----
    const float* xn = xg + (size_t)n * 4096;
    for (int t = tid; t < 1024; t += 128) {
        float4 v = ((const float4*)xn)[t];
        int r = t >> 4, c = (t & 15) << 2;
        *(float4*)&Xs[r * PAD + c] = v;
    }
    __syncthreads();
    // ---- build XT (transpose) ----
    for (int t = tid; t < 1024; t += 128) {
        int dd = t >> 4, i0 = (t & 15) << 2;
        float4 v;
        v.x = Xs[(i0 + 0) * PAD + dd];
        v.y = Xs[(i0 + 1) * PAD + dd];
        v.z = Xs[(i0 + 2) * PAD + dd];
        v.w = Xs[(i0 + 3) * PAD + dd];
        *(float4*)&XT[dd * PAD + i0] = v;
    }
    __syncthreads();
    // Unit-norm inputs; exp-map preserves unit norm: ||v||^2 = 1 - dc^2.
    // Warps own their Ws rows (o = oc + 8k) -> warp-local sync inside loop.

    const float HI = 1.0f - 1e-7f;
    float av[8][4];   // a[o=oc+8k][dd=ic+16j], live F-phase -> epilogue

    #pragma unroll 1
    for (int it = 0; it < 3; ++it) {
        float corr[8];

        if (it == 0) {
            // ===== iter-0: D[o][i] = x0 . x_i for ALL o -> 4 packed dots =====
            u64 dp2[4];
            #pragma unroll
            for (int j = 0; j < 4; ++j) dp2[j] = 0ull;
            #pragma unroll 4
            for (int dd = 0; dd < 64; dd += 4) {
                ulonglong2 x0p = *(const ulonglong2*)&Xs[dd];  // row 0, broadcast
                #pragma unroll
                for (int j = 0; j < 4; ++j) {
                    ulonglong2 xp = *(const ulonglong2*)&Xs[(ic + 16 * j) * PAD + dd];
                    dp2[j] = ffma2(x0p.x, xp.x, dp2[j]);
                    dp2[j] = ffma2(x0p.y, xp.y, dp2[j]);
                }
            }
            float dcv[4], ffv[4], x0v[4];
            #pragma unroll
            for (int j = 0; j < 4; ++j) {
                float draw = hadd2(dp2[j]);
                float dc   = fminf(fmaxf(draw, -HI), HI);
                dcv[j] = dc;
                ffv[j] = acos_fast(dc) * rsqrtf(fmaf(-dc, dc, 1.0f));
                x0v[j] = Xs[ic + 16 * j];     // a_o = x_0, o-independent
            }
            #pragma unroll
            for (int k = 0; k < 8; ++k) {
                int o = oc + 8 * k;
                float cr = 0.f;
                #pragma unroll
                for (int j = 0; j < 4; ++j) {
                    int i = ic + 16 * j;
                    float F = g_wT[o * 64 + i] * ffv[j];
                    Ws[o * PAD + i] = F;
                    cr = fmaf(F, dcv[j], cr);
                    av[k][j] = x0v[j];
                }
                corr[k] = cr;
            }
        } else {
            // ===== GEMM1 (f32x2 along dd): D[o][i] = sum_dd A[o][dd]*X[i][dd]
            u64 acc2[8][4];
            #pragma unroll
            for (int k = 0; k < 8; ++k)
                #pragma unroll
                for (int j = 0; j < 4; ++j) acc2[k][j] = 0ull;

            #pragma unroll 4
            for (int dd = 0; dd < 64; dd += 4) {
                ulonglong2 xp[4];
                #pragma unroll
                for (int j = 0; j < 4; ++j)
                    xp[j] = *(const ulonglong2*)&Xs[(ic + 16 * j) * PAD + dd];
                #pragma unroll
                for (int k = 0; k < 8; ++k) {
                    ulonglong2 ap = *(const ulonglong2*)&Ws[(oc + 8 * k) * PAD + dd];
                    #pragma unroll
                    for (int j = 0; j < 4; ++j) {
                        acc2[k][j] = ffma2(ap.x, xp[j].x, acc2[k][j]);
                        acc2[k][j] = ffma2(ap.y, xp[j].y, acc2[k][j]);
                    }
                }
            }
            __syncwarp();  // all A reads done before F overwrites Ws

            // ===== F-phase: grab a into regs, then overwrite Ws with F
            #pragma unroll
            for (int k = 0; k < 8; ++k) {
                int o = oc + 8 * k;
                float cr = 0.f;
                #pragma unroll
                for (int j = 0; j < 4; ++j) {
                    int i = ic + 16 * j;
                    av[k][j] = Ws[o * PAD + i];      // A value (same addr, pre-write)
                    float draw  = hadd2(acc2[k][j]);
                    float dc    = fminf(fmaxf(draw, -HI), HI);
                    float theta = acos_fast(dc);
                    float nv2   = fmaf(-dc, dc, 1.0f);
                    float f     = theta * rsqrtf(nv2);
                    float F     = g_wT[o * 64 + i] * f;
                    Ws[o * PAD + i] = F;
                    cr = fmaf(F, dc, cr);
                }
                corr[k] = cr;
            }
        }
        __syncwarp();  // warp's F rows complete in Ws

        // ===== GEMM2 (f32x2 along i via XT, no broadcasts):
        //       G[o][dd] = sum_i F[o][i] * XT[dd][i], dd = ic+16j
        u64 g2[8][4];
        #pragma unroll
        for (int k = 0; k < 8; ++k)
            #pragma unroll
            for (int j = 0; j < 4; ++j) g2[k][j] = 0ull;

        #pragma unroll 4
        for (int i4 = 0; i4 < 64; i4 += 4) {
            ulonglong2 xtp[4];
            #pragma unroll
            for (int j = 0; j < 4; ++j)
                xtp[j] = *(const ulonglong2*)&XT[(ic + 16 * j) * PAD + i4];
            #pragma unroll
            for (int k = 0; k < 8; ++k) {
                ulonglong2 fp = *(const ulonglong2*)&Ws[(oc + 8 * k) * PAD + i4];
                #pragma unroll
                for (int j = 0; j < 4; ++j) {
                    g2[k][j] = ffma2(fp.x, xtp[j].x, g2[k][j]);
                    g2[k][j] = ffma2(fp.y, xtp[j].y, g2[k][j]);
                }
            }
        }

        // corr reduction deferred here: SHFL latency overlapped GEMM2 issue.
        // Full-mask shfl also converges the warp before the A-stores below.
        #pragma unroll
        for (int k = 0; k < 8; ++k) {
            #pragma unroll
            for (int s = 1; s < 16; s <<= 1)
                corr[k] += __shfl_xor_sync(0xffffffffu, corr[k], s);
        }

        // ===== exp-map update (scalar, dd = ic+16j) =====
        #pragma unroll
        for (int k = 0; k < 8; ++k) {
            int o = oc + 8 * k;
            float grad[4];
            float gn2 = 0.f;
            #pragma unroll
            for (int j = 0; j < 4; ++j) {
                grad[j] = hadd2(g2[k][j]) - corr[k] * av[k][j];
                gn2 = fmaf(grad[j], grad[j], gn2);
            }
            #pragma unroll
            for (int s = 1; s < 16; s <<= 1)
                gn2 += __shfl_xor_sync(0xffffffffu, gn2, s);
            float inv = rsqrtf(fmaxf(gn2, 1e-30f));
            float gn = gn2 * inv;                 // sqrt(gn2)
            float sg, cg;
            __sincosf(gn, &sg, &cg);
            float sc = (gn2 < 1e-14f) ? 1.0f : sg * inv;
            if (gn2 < 1e-14f) cg = 1.0f;

            if (it == 2) {
                #pragma unroll
                for (int j = 0; j < 4; ++j) {
                    int dd = ic + 16 * j;
                    out[(size_t)n * 4096 + o * 64 + dd] = fmaf(cg, av[k][j], sc * grad[j]);
                }
            } else {
                #pragma unroll
                for (int j = 0; j < 4; ++j) {
                    int dd = ic + 16 * j;
                    float an = fmaf(cg, av[k][j], sc * grad[j]);
                    Ws[o * PAD + dd] = an;        // A for next iter's GEMM1
                }
            }
        }
        __syncwarp();  // warp's A rows ready for its next iteration
    }
}

extern "C" void kernel_launch(void* const* d_in, const int* in_sizes, int n_in,
                              void* d_out, int out_size) {
    const float* x    = (const float*)d_in[0];   // (4,256,64,64)
    const float* wraw = (const float*)d_in[1];   // (64,64)
    float* out = (float*)d_out;                  // (4,256,64,64)

    cudaFuncSetAttribute(mfd_kernel, cudaFuncAttributeMaxDynamicSharedMemorySize, SMEM_BYTES);

    wprep_kernel<<<1, 64>>>(wraw);
    mfd_kernel<<<1024, 128, SMEM_BYTES>>>(x, out);
}

// round 15
// speedup vs baseline: 1.1803x; 1.1803x over previous
#include <cuda_runtime.h>
#include <math.h>

#define PAD 68
#define ARR (64 * PAD)
#define SMEM_FLOATS (3 * ARR + 32)
#define SMEM_BYTES (SMEM_FLOATS * 4)

typedef unsigned long long u64;

// column-softmaxed weights, o-major: g_wT[o*64 + i] = w[i][o]
__device__ float g_wT[64 * 64];

static __device__ __forceinline__ u64 ffma2(u64 a, u64 b, u64 c) {
    u64 d; asm("fma.rn.f32x2 %0,%1,%2,%3;" : "=l"(d) : "l"(a), "l"(b), "l"(c)); return d;
}
static __device__ __forceinline__ u64 fmul2(u64 a, u64 b) {
    u64 d; asm("mul.rn.f32x2 %0,%1,%2;" : "=l"(d) : "l"(a), "l"(b)); return d;
}
static __device__ __forceinline__ float hadd2(u64 v) {
    float lo, hi; asm("mov.b64 {%0,%1},%2;" : "=f"(lo), "=f"(hi) : "l"(v));
    return lo + hi;
}
static __device__ __forceinline__ void unpack2(u64 v, float& lo, float& hi) {
    asm("mov.b64 {%0,%1},%2;" : "=f"(lo), "=f"(hi) : "l"(v));
}
static __device__ __forceinline__ u64 bcast2(float f) {
    u64 d; asm("mov.b64 %0,{%1,%1};" : "=l"(d) : "f"(f)); return d;
}

// acos via A&S 4.4.45 7-term poly, Estrin form: abs err ~2e-8 on [-1,1]
// Input pre-clamped to |x| <= 1-1e-7, so om >= 1e-7 (rsqrt safe).
static __device__ __forceinline__ float acos_fast(float x) {
    float ax = fabsf(x);
    float om = 1.0f - ax;
    float s = om * rsqrtf(om);   // sqrt(1-ax), MUFU issued early
    float x2 = ax * ax;
    float x4 = x2 * x2;
    float p01 = fmaf(ax, -0.2145988016f, 1.5707963050f);
    float p23 = fmaf(ax, -0.0501743046f, 0.0889789874f);
    float p45 = fmaf(ax, -0.0170881256f, 0.0308918810f);
    float p67 = fmaf(ax, -0.0012624911f, 0.0066700901f);
    float q0 = fmaf(p23, x2, p01);
    float q1 = fmaf(p67, x2, p45);
    float p = fmaf(q1, x4, q0);
    float r = p * s;
    return (x < 0.0f) ? 3.14159265358979f - r : r;
}

__global__ void wprep_kernel(const float* __restrict__ wraw) {
    int o = threadIdx.x;  // 64 threads, one output column each
    float s = 0.f;
    #pragma unroll 8
    for (int i = 0; i < 64; ++i) s += expf(wraw[i * 64 + o]);
    float inv = 1.0f / s;
    #pragma unroll 8
    for (int i = 0; i < 64; ++i) g_wT[o * 64 + i] = expf(wraw[i * 64 + o]) * inv;
}

__global__ __launch_bounds__(128, 4) void mfd_kernel(const float* __restrict__ xg,
                                                     float* __restrict__ out) {
    extern __shared__ float sm[];
    float* Xs  = sm;              // [64][PAD]  x rows (dd-contiguous)
    float* As  = Xs + ARR;        // [64][PAD]  current iterate a
    float* Fs  = As + ARR;        // [64][PAD]  F matrix (i-contiguous per o-row)

    const int n   = blockIdx.x;
    const int tid = threadIdx.x;
    const int oc  = tid >> 4;     // 0..7  (warp = {2w, 2w+1} oc values)
    const int ic  = tid & 15;     // 0..15
    const int dq  = 4 * ic;       // thread's dd-quad base (GEMM2/epilogue)

    // ---- load x tile (coalesced float4) ----
    const float* xn = xg + (size_t)n * 4096;
    for (int t = tid; t < 1024; t += 128) {
        float4 v = ((const float4*)xn)[t];
        int r = t >> 4, c = (t & 15) << 2;
        *(float4*)&Xs[r * PAD + c] = v;
    }
    __syncthreads();

    // ---- init a_o = x_0 for all o ----
    for (int t = tid; t < 1024; t += 128) {
        int r = t >> 4, c = (t & 15) << 2;
        *(float4*)&As[r * PAD + c] = *(float4*)&Xs[c];
    }
    __syncthreads();
    // Unit-norm inputs; exp-map preserves unit norm to rounding, so
    // ||v||^2 = 1 - dc^2 (branch-free). Warps own their As/Fs rows
    // (o = oc + 8k, oc in {2w,2w+1}) -> warp-local sync inside the loop.

    const float HI = 1.0f - 1e-7f;

    #pragma unroll 1
    for (int it = 0; it < 3; ++it) {
        float corr[8];

        if (it == 0) {
            // ===== iter-0: D[o][i] = x0 . x_i for ALL o -> 4 direct dots =====
            u64 dp2[4];
            #pragma unroll
            for (int j = 0; j < 4; ++j) dp2[j] = 0ull;
            #pragma unroll 4
            for (int dd = 0; dd < 64; dd += 4) {
                ulonglong2 x0p = *(const ulonglong2*)&Xs[dd];  // row 0, broadcast
                #pragma unroll
                for (int j = 0; j < 4; ++j) {
                    ulonglong2 xp = *(const ulonglong2*)&Xs[(ic + 16 * j) * PAD + dd];
                    dp2[j] = ffma2(x0p.x, xp.x, dp2[j]);
                    dp2[j] = ffma2(x0p.y, xp.y, dp2[j]);
                }
            }
            float dcv[4], ffv[4];
            #pragma unroll
            for (int j = 0; j < 4; ++j) {
                float draw = hadd2(dp2[j]);
                float dc   = fminf(fmaxf(draw, -HI), HI);
                dcv[j] = dc;
                ffv[j] = acos_fast(dc) * rsqrtf(fmaf(-dc, dc, 1.0f));
            }
            #pragma unroll
            for (int k = 0; k < 8; ++k) {
                int o = oc + 8 * k;
                float cr = 0.f;
                #pragma unroll
                for (int j = 0; j < 4; ++j) {
                    int i = ic + 16 * j;
                    float F = g_wT[o * 64 + i] * ffv[j];
                    Fs[o * PAD + i] = F;
                    cr = fmaf(F, dcv[j], cr);
                }
                corr[k] = cr;
            }
        } else {
            // ===== GEMM1 (f32x2 along dd): D[o][i] = sum_dd A[o][dd]*X[i][dd]
            u64 acc2[8][4];
            #pragma unroll
            for (int k = 0; k < 8; ++k)
                #pragma unroll
                for (int j = 0; j < 4; ++j) acc2[k][j] = 0ull;

            #pragma unroll 4
            for (int dd = 0; dd < 64; dd += 4) {
                ulonglong2 xp[4];
                #pragma unroll
                for (int j = 0; j < 4; ++j)
                    xp[j] = *(const ulonglong2*)&Xs[(ic + 16 * j) * PAD + dd];
                #pragma unroll
                for (int k = 0; k < 8; ++k) {
                    ulonglong2 ap = *(const ulonglong2*)&As[(oc + 8 * k) * PAD + dd];
                    #pragma unroll
                    for (int j = 0; j < 4; ++j) {
                        acc2[k][j] = ffma2(ap.x, xp[j].x, acc2[k][j]);
                        acc2[k][j] = ffma2(ap.y, xp[j].y, acc2[k][j]);
                    }
                }
            }

            // ===== F[o][i] = w[i][o]*theta/||v||, partial corr = sum_i F*dc
            #pragma unroll
            for (int k = 0; k < 8; ++k) {
                int o = oc + 8 * k;
                float cr = 0.f;
                #pragma unroll
                for (int j = 0; j < 4; ++j) {
                    int i = ic + 16 * j;
                    float draw  = hadd2(acc2[k][j]);
                    float dc    = fminf(fmaxf(draw, -HI), HI);
                    float theta = acos_fast(dc);
                    float nv2   = fmaf(-dc, dc, 1.0f);
                    float f     = theta * rsqrtf(nv2);
                    float F     = g_wT[o * 64 + i] * f;
                    Fs[o * PAD + i] = F;
                    cr = fmaf(F, dc, cr);
                }
                corr[k] = cr;
            }
        }
        __syncwarp();  // warp's Fs rows complete

        // ===== GEMM2 (f32x2 along dd-quad, F broadcast):
        //       G[o][dd] = sum_i F[o][i] * X[i][dd], dd in {4ic..4ic+3}
        u64 g2[8][2];
        #pragma unroll
        for (int k = 0; k < 8; ++k) { g2[k][0] = 0ull; g2[k][1] = 0ull; }

        #pragma unroll 4
        for (int i4 = 0; i4 < 64; i4 += 4) {
            ulonglong2 xq[4];
            #pragma unroll
            for (int r = 0; r < 4; ++r)
                xq[r] = *(const ulonglong2*)&Xs[(i4 + r) * PAD + dq];
            #pragma unroll
            for (int k = 0; k < 8; ++k) {
                ulonglong2 fp = *(const ulonglong2*)&Fs[(oc + 8 * k) * PAD + i4];
                float f0, f1, f2, f3;
                unpack2(fp.x, f0, f1);
                unpack2(fp.y, f2, f3);
                u64 b0 = bcast2(f0), b1 = bcast2(f1), b2 = bcast2(f2), b3 = bcast2(f3);
                g2[k][0] = ffma2(b0, xq[0].x, g2[k][0]);
                g2[k][0] = ffma2(b1, xq[1].x, g2[k][0]);
                g2[k][0] = ffma2(b2, xq[2].x, g2[k][0]);
                g2[k][0] = ffma2(b3, xq[3].x, g2[k][0]);
                g2[k][1] = ffma2(b0, xq[0].y, g2[k][1]);
                g2[k][1] = ffma2(b1, xq[1].y, g2[k][1]);
                g2[k][1] = ffma2(b2, xq[2].y, g2[k][1]);
                g2[k][1] = ffma2(b3, xq[3].y, g2[k][1]);
            }
        }

        // corr reduction deferred here: SHFL latency overlapped GEMM2 issue
        #pragma unroll
        for (int k = 0; k < 8; ++k) {
            #pragma unroll
            for (int s = 1; s < 16; s <<= 1)
                corr[k] += __shfl_xor_sync(0xffffffffu, corr[k], s);
        }

        // ===== exp-map update (f32x2 on the dd-quad) =====
        #pragma unroll
        for (int k = 0; k < 8; ++k) {
            int o = oc + 8 * k;
            ulonglong2 aq = *(const ulonglong2*)&As[o * PAD + dq];
            u64 ncb = bcast2(-corr[k]);
            u64 gr0 = ffma2(ncb, aq.x, g2[k][0]);
            u64 gr1 = ffma2(ncb, aq.y, g2[k][1]);
            float q0, q1, q2, q3;
            unpack2(gr0, q0, q1);
            unpack2(gr1, q2, q3);
            float gn2 = q0 * q0;
            gn2 = fmaf(q1, q1, gn2);
            gn2 = fmaf(q2, q2, gn2);
            gn2 = fmaf(q3, q3, gn2);
            #pragma unroll
            for (int s = 1; s < 16; s <<= 1)
                gn2 += __shfl_xor_sync(0xffffffffu, gn2, s);
            float inv = rsqrtf(fmaxf(gn2, 1e-30f));
            float gn = gn2 * inv;                 // sqrt(gn2)
            float sg, cg;
            __sincosf(gn, &sg, &cg);
            float sc = (gn2 < 1e-14f) ? 1.0f : sg * inv;
            if (gn2 < 1e-14f) cg = 1.0f;

            u64 cgb = bcast2(cg), scb = bcast2(sc);
            ulonglong2 an;
            an.x = ffma2(cgb, aq.x, fmul2(scb, gr0));
            an.y = ffma2(cgb, aq.y, fmul2(scb, gr1));

            if (it == 2) {
                *(ulonglong2*)&out[(size_t)n * 4096 + o * 64 + dq] = an;
            } else {
                *(ulonglong2*)&As[o * PAD + dq] = an;
            }
        }
        __syncwarp();  // warp's As rows ready for its next iteration
    }
}

extern "C" void kernel_launch(void* const* d_in, const int* in_sizes, int n_in,
                              void* d_out, int out_size) {
    const float* x    = (const float*)d_in[0];   // (4,256,64,64)
    const float* wraw = (const float*)d_in[1];   // (64,64)
    float* out = (float*)d_out;                  // (4,256,64,64)

    cudaFuncSetAttribute(mfd_kernel, cudaFuncAttributeMaxDynamicSharedMemorySize, SMEM_BYTES);

    wprep_kernel<<<1, 64>>>(wraw);
    mfd_kernel<<<1024, 128, SMEM_BYTES>>>(x, out);
}